// round 12
// baseline (speedup 1.0000x reference)
#include <cuda_runtime.h>

// BoundaryConsistencyLoss — SINGLE-KERNEL version.
// Direct-from-global register-sliding accum (KW=4, 1-deep row prefetch),
// atomicAdd window accumulation, threadfence last-block final reduction.
// B=512, L=16384, C=2, window=5.
//
// p = softmax(pred,-1)[...,1] = sigmoid(p1-p0)
// Window sums (w=5) of m, t*m (int) and p*m, p^2*m (float); t in {0,1} => st2m==stm.
// pvar = sp2m/denom - pmean^2 ; tvar = tmean*(1-tmean)  (exact; msum==0 => both 0).
// valid_w = (sum_b msum > 0) === OR over batches of (window has any mask).
//
// Replay determinism: g_win_mse/g_win_valid/g_ticket are zero-initialized at
// module load; the last block of every launch re-zeroes them and resets the
// ticket, so each graph replay starts from the identical state.

#define BB_B      512
#define LL        16384
#define WIN       5
#define NW        (LL - WIN + 1)            // 16380
#define THREADS   128
#define KW        4
#define WCHUNK    (THREADS * KW)            // 512
#define NCHUNK    (LL / WCHUNK)             // 32
#define BGROUPS   64
#define BPG       (BB_B / BGROUPS)          // 8
#define NE        (KW + WIN - 1)            // 8 elements per thread per row
#define NBLOCKS   (NCHUNK * BGROUPS)        // 2048

__device__ float    g_win_mse[LL];          // per-window sum over all batches of d^2
__device__ unsigned g_win_valid[LL / 32];   // per-window any-mask bit
__device__ unsigned g_ticket;               // completion counter

__device__ __forceinline__ float fsigmoid(float x) {
    return __fdividef(1.0f, 1.0f + __expf(-x));
}

struct RowRegs {
    float4 pr[4];          // 8 pred pairs
    int4   tt[2], mm[2];   // 8 targets, 8 masks
};

__device__ __forceinline__ void load_row(RowRegs& r,
                                         const float* __restrict__ preds,
                                         const int* __restrict__ targets,
                                         const int* __restrict__ mask,
                                         size_t rb, int base)
{
    const float4* p4 = (const float4*)preds + ((rb + (size_t)base) >> 1);
    const int4*   t4 = (const int4*)(targets + rb + base);
    const int4*   m4 = (const int4*)(mask    + rb + base);
#pragma unroll
    for (int q = 0; q < 4; q++) r.pr[q] = __ldg(&p4[q]);
#pragma unroll
    for (int q = 0; q < 2; q++) { r.tt[q] = __ldg(&t4[q]); r.mm[q] = __ldg(&m4[q]); }
}

__global__ __launch_bounds__(THREADS)
void bcl_kernel(const float* __restrict__ preds,
                const int*   __restrict__ targets,
                const int*   __restrict__ mask,
                float*       __restrict__ out)
{
    const int tid  = threadIdx.x;
    const int w0   = blockIdx.x * WCHUNK;
    const int base = w0 + tid * KW;
    const int b0   = blockIdx.y * BPG;
    const bool interior = (base + NE) <= LL;   // false only for last thread of last chunk

    float acc_mse[KW];
#pragma unroll
    for (int j = 0; j < KW; j++) acc_mse[j] = 0.f;
    unsigned vmask = 0;                        // bit j: window base+j had any mask

    if (interior) {
        RowRegs cur, nxt;
        load_row(cur, preds, targets, mask, (size_t)b0 * LL, base);

#pragma unroll
        for (int bi = 0; bi < BPG; bi++) {
            if (bi + 1 < BPG)
                load_row(nxt, preds, targets, mask, (size_t)(b0 + bi + 1) * LL, base);

            float pv[NE];
            int   mv[NE], tv[NE];
#pragma unroll
            for (int q = 0; q < 4; q++) {
                pv[q*2+0] = fsigmoid(cur.pr[q].y - cur.pr[q].x);
                pv[q*2+1] = fsigmoid(cur.pr[q].w - cur.pr[q].z);
            }
#pragma unroll
            for (int q = 0; q < 2; q++) {
                tv[q*4+0] = cur.tt[q].x; tv[q*4+1] = cur.tt[q].y;
                tv[q*4+2] = cur.tt[q].z; tv[q*4+3] = cur.tt[q].w;
                mv[q*4+0] = cur.mm[q].x; mv[q*4+1] = cur.mm[q].y;
                mv[q*4+2] = cur.mm[q].z; mv[q*4+3] = cur.mm[q].w;
            }

            int   tm[NE];
            float pm[NE], p2m[NE];
#pragma unroll
            for (int e = 0; e < NE; e++) {
                const int mi = mv[e];
                tm[e]  = tv[e] & mi;
                const float fm = (float)mi;
                pm[e]  = pv[e] * fm;
                p2m[e] = pv[e] * pm[e];
            }

            int   smi  = mv[0]+mv[1]+mv[2]+mv[3]+mv[4];
            int   stmi = tm[0]+tm[1]+tm[2]+tm[3]+tm[4];
            float spm  = pm[0]+pm[1]+pm[2]+pm[3]+pm[4];
            float sp2m = p2m[0]+p2m[1]+p2m[2]+p2m[3]+p2m[4];

#pragma unroll
            for (int j = 0; j < KW; j++) {
                const float sm    = (float)smi;
                const float rden  = __fdividef(1.0f, fmaxf(sm, 1.0f));
                const float pmean = spm * rden;
                const float pvar  = sp2m * rden - pmean * pmean;
                const float tmean = (float)stmi * rden;
                const float tvar  = tmean - tmean * tmean;
                const float d = pvar - tvar;
                acc_mse[j] += d * d;
                vmask |= (unsigned)(smi != 0) << j;
                if (j < KW - 1) {
                    smi  += mv[j+WIN] - mv[j];
                    stmi += tm[j+WIN] - tm[j];
                    spm  += pm[j+WIN] - pm[j];
                    sp2m += p2m[j+WIN] - p2m[j];
                }
            }
            cur = nxt;
        }
    } else {
        // tail thread: guarded scalar path (rare, correctness only)
        for (int bi = 0; bi < BPG; bi++) {
            const size_t rb = (size_t)(b0 + bi) * LL;
            float pv[NE]; int mv[NE], tv[NE];
#pragma unroll
            for (int e = 0; e < NE; e++) {
                const int idx = base + e;
                if (idx < LL) {
                    float a = __ldg(&preds[(rb + idx) * 2 + 0]);
                    float b = __ldg(&preds[(rb + idx) * 2 + 1]);
                    pv[e] = fsigmoid(b - a);
                    tv[e] = __ldg(&targets[rb + idx]);
                    mv[e] = __ldg(&mask[rb + idx]);
                } else { pv[e] = 0.f; tv[e] = 0; mv[e] = 0; }
            }
            int tm[NE]; float pm[NE], p2m[NE];
#pragma unroll
            for (int e = 0; e < NE; e++) {
                const int mi = mv[e];
                tm[e] = tv[e] & mi;
                const float fm = (float)mi;
                pm[e] = pv[e] * fm;
                p2m[e] = pv[e] * pm[e];
            }
            int   smi  = mv[0]+mv[1]+mv[2]+mv[3]+mv[4];
            int   stmi = tm[0]+tm[1]+tm[2]+tm[3]+tm[4];
            float spm  = pm[0]+pm[1]+pm[2]+pm[3]+pm[4];
            float sp2m = p2m[0]+p2m[1]+p2m[2]+p2m[3]+p2m[4];
#pragma unroll
            for (int j = 0; j < KW; j++) {
                const float sm    = (float)smi;
                const float rden  = __fdividef(1.0f, fmaxf(sm, 1.0f));
                const float pmean = spm * rden;
                const float pvar  = sp2m * rden - pmean * pmean;
                const float tmean = (float)stmi * rden;
                const float tvar  = tmean - tmean * tmean;
                const float d = pvar - tvar;
                acc_mse[j] += d * d;
                vmask |= (unsigned)(smi != 0) << j;
                if (j < KW - 1) {
                    smi  += mv[j+WIN] - mv[j];
                    stmi += tm[j+WIN] - tm[j];
                    spm  += pm[j+WIN] - pm[j];
                    sp2m += p2m[j+WIN] - p2m[j];
                }
            }
        }
    }

    // Accumulate into the global per-window array (64 colliding blocks per
    // address, spread over 16K addresses -> negligible LTS serialization).
    float* wm = &g_win_mse[base];
    atomicAdd(&wm[0], acc_mse[0]);
    atomicAdd(&wm[1], acc_mse[1]);
    atomicAdd(&wm[2], acc_mse[2]);
    atomicAdd(&wm[3], acc_mse[3]);
    if (vmask)
        atomicOr(&g_win_valid[base >> 5], vmask << (base & 31));

    // Last-block final reduction (threadfence reduction pattern).
    __threadfence();
    __syncthreads();
    __shared__ unsigned s_ticket;
    if (tid == 0) s_ticket = atomicAdd(&g_ticket, 1u);
    __syncthreads();
    if (s_ticket != NBLOCKS - 1) return;

    // This block runs after all atomics are globally visible.
    float lmse = 0.f, lcnt = 0.f;
#pragma unroll 8
    for (int w = tid; w < LL; w += THREADS) {
        const unsigned vw = g_win_valid[w >> 5];
        const float    mv = g_win_mse[w];
        if (w < NW && ((vw >> (w & 31)) & 1u)) {
            lmse += mv;
            lcnt += 1.f;
        }
        g_win_mse[w] = 0.f;                      // restore state for next replay
    }
#pragma unroll
    for (int v = tid; v < LL / 32; v += THREADS)
        g_win_valid[v] = 0u;

#pragma unroll
    for (int o = 16; o > 0; o >>= 1) {
        lmse += __shfl_down_sync(0xffffffffu, lmse, o);
        lcnt += __shfl_down_sync(0xffffffffu, lcnt, o);
    }
    __shared__ float smse[4], scnt[4];
    const int wid = tid >> 5, lid = tid & 31;
    if (lid == 0) { smse[wid] = lmse; scnt[wid] = lcnt; }
    __syncthreads();
    if (tid == 0) {
        float a = smse[0] + smse[1] + smse[2] + smse[3];
        float c = scnt[0] + scnt[1] + scnt[2] + scnt[3];
        out[0] = (a * (1.0f / (float)BB_B)) / fmaxf(c, 1.0f);  // weight == 1.0
        g_ticket = 0;                            // reset for next replay
    }
}

extern "C" void kernel_launch(void* const* d_in, const int* in_sizes, int n_in,
                              void* d_out, int out_size)
{
    const float* preds   = (const float*)d_in[0];
    const int*   targets = (const int*)  d_in[1];
    const int*   mask    = (const int*)  d_in[2];

    dim3 gridA(NCHUNK, BGROUPS);             // 32 x 64 = 2048 blocks
    bcl_kernel<<<gridA, THREADS>>>(preds, targets, mask, (float*)d_out);
}

// round 13
// speedup vs baseline: 1.1975x; 1.1975x over previous
#include <cuda_runtime.h>

// BoundaryConsistencyLoss — TWO-KERNEL version.
// K1: direct-from-global register-sliding accum (KW=4, 1-deep row prefetch,
//     bitmask validity) — identical to the proven 28.3us kernel.
// K2: one reduce kernel (64 blocks): group-sum + validity + atomic combine +
//     64-block ticket; last block writes out and resets state for replay.
// B=512, L=16384, C=2, window=5.
//
// p = softmax(pred,-1)[...,1] = sigmoid(p1-p0)
// Window sums (w=5) of m, t*m (int) and p*m, p^2*m (float); t in {0,1} => st2m==stm.
// pvar = sp2m/denom - pmean^2 ; tvar = tmean*(1-tmean)  (exact; msum==0 => both 0).
// valid_w = (sum_b msum > 0) === OR over batches of (window has any mask).

#define BB_B      512
#define LL        16384
#define WIN       5
#define NW        (LL - WIN + 1)            // 16380
#define THREADS   128
#define KW        4
#define WCHUNK    (THREADS * KW)            // 512
#define NCHUNK    (LL / WCHUNK)             // 32
#define BGROUPS   64
#define BPG       (BB_B / BGROUPS)          // 8
#define NE        (KW + WIN - 1)            // 8 elements per thread per row
#define VBYTES    (LL / KW)                 // 4096 validity bytes per group
#define RBLOCKS   64

// Scratch (device globals — allocation-free). Partials written exactly once
// per launch; g_acc/g_ticket are zero at load and re-zeroed by the last
// reduce block each launch -> replays start from identical state.
__device__ float         g_part_mse[BGROUPS * LL];
__device__ unsigned char g_valid   [BGROUPS * VBYTES];
__device__ float         g_acc[2];
__device__ unsigned      g_ticket;

__device__ __forceinline__ float fsigmoid(float x) {
    return __fdividef(1.0f, 1.0f + __expf(-x));
}

struct RowRegs {
    float4 pr[4];          // 8 pred pairs
    int4   tt[2], mm[2];   // 8 targets, 8 masks
};

__device__ __forceinline__ void load_row(RowRegs& r,
                                         const float* __restrict__ preds,
                                         const int* __restrict__ targets,
                                         const int* __restrict__ mask,
                                         size_t rb, int base)
{
    const float4* p4 = (const float4*)preds + ((rb + (size_t)base) >> 1);
    const int4*   t4 = (const int4*)(targets + rb + base);
    const int4*   m4 = (const int4*)(mask    + rb + base);
#pragma unroll
    for (int q = 0; q < 4; q++) r.pr[q] = __ldg(&p4[q]);
#pragma unroll
    for (int q = 0; q < 2; q++) { r.tt[q] = __ldg(&t4[q]); r.mm[q] = __ldg(&m4[q]); }
}

__global__ __launch_bounds__(THREADS)
void bcl_accum_kernel(const float* __restrict__ preds,
                      const int*   __restrict__ targets,
                      const int*   __restrict__ mask)
{
    const int tid  = threadIdx.x;
    const int w0   = blockIdx.x * WCHUNK;
    const int base = w0 + tid * KW;
    const int b0   = blockIdx.y * BPG;
    const bool interior = (base + NE) <= LL;   // false only for last thread of last chunk

    float acc_mse[KW];
#pragma unroll
    for (int j = 0; j < KW; j++) acc_mse[j] = 0.f;
    unsigned vmask = 0;                        // bit j: window base+j had any mask

    if (interior) {
        RowRegs cur, nxt;
        load_row(cur, preds, targets, mask, (size_t)b0 * LL, base);

#pragma unroll
        for (int bi = 0; bi < BPG; bi++) {
            if (bi + 1 < BPG)
                load_row(nxt, preds, targets, mask, (size_t)(b0 + bi + 1) * LL, base);

            float pv[NE];
            int   mv[NE], tv[NE];
#pragma unroll
            for (int q = 0; q < 4; q++) {
                pv[q*2+0] = fsigmoid(cur.pr[q].y - cur.pr[q].x);
                pv[q*2+1] = fsigmoid(cur.pr[q].w - cur.pr[q].z);
            }
#pragma unroll
            for (int q = 0; q < 2; q++) {
                tv[q*4+0] = cur.tt[q].x; tv[q*4+1] = cur.tt[q].y;
                tv[q*4+2] = cur.tt[q].z; tv[q*4+3] = cur.tt[q].w;
                mv[q*4+0] = cur.mm[q].x; mv[q*4+1] = cur.mm[q].y;
                mv[q*4+2] = cur.mm[q].z; mv[q*4+3] = cur.mm[q].w;
            }

            int   tm[NE];
            float pm[NE], p2m[NE];
#pragma unroll
            for (int e = 0; e < NE; e++) {
                const int mi = mv[e];
                tm[e]  = tv[e] & mi;
                const float fm = (float)mi;
                pm[e]  = pv[e] * fm;
                p2m[e] = pv[e] * pm[e];
            }

            int   smi  = mv[0]+mv[1]+mv[2]+mv[3]+mv[4];
            int   stmi = tm[0]+tm[1]+tm[2]+tm[3]+tm[4];
            float spm  = pm[0]+pm[1]+pm[2]+pm[3]+pm[4];
            float sp2m = p2m[0]+p2m[1]+p2m[2]+p2m[3]+p2m[4];

#pragma unroll
            for (int j = 0; j < KW; j++) {
                const float sm    = (float)smi;
                const float rden  = __fdividef(1.0f, fmaxf(sm, 1.0f));
                const float pmean = spm * rden;
                const float pvar  = sp2m * rden - pmean * pmean;
                const float tmean = (float)stmi * rden;
                const float tvar  = tmean - tmean * tmean;
                const float d = pvar - tvar;
                acc_mse[j] += d * d;
                vmask |= (unsigned)(smi != 0) << j;
                if (j < KW - 1) {
                    smi  += mv[j+WIN] - mv[j];
                    stmi += tm[j+WIN] - tm[j];
                    spm  += pm[j+WIN] - pm[j];
                    sp2m += p2m[j+WIN] - p2m[j];
                }
            }
            cur = nxt;
        }
    } else {
        // tail thread: guarded scalar path (rare, correctness only)
        for (int bi = 0; bi < BPG; bi++) {
            const size_t rb = (size_t)(b0 + bi) * LL;
            float pv[NE]; int mv[NE], tv[NE];
#pragma unroll
            for (int e = 0; e < NE; e++) {
                const int idx = base + e;
                if (idx < LL) {
                    float a = __ldg(&preds[(rb + idx) * 2 + 0]);
                    float b = __ldg(&preds[(rb + idx) * 2 + 1]);
                    pv[e] = fsigmoid(b - a);
                    tv[e] = __ldg(&targets[rb + idx]);
                    mv[e] = __ldg(&mask[rb + idx]);
                } else { pv[e] = 0.f; tv[e] = 0; mv[e] = 0; }
            }
            int tm[NE]; float pm[NE], p2m[NE];
#pragma unroll
            for (int e = 0; e < NE; e++) {
                const int mi = mv[e];
                tm[e] = tv[e] & mi;
                const float fm = (float)mi;
                pm[e] = pv[e] * fm;
                p2m[e] = pv[e] * pm[e];
            }
            int   smi  = mv[0]+mv[1]+mv[2]+mv[3]+mv[4];
            int   stmi = tm[0]+tm[1]+tm[2]+tm[3]+tm[4];
            float spm  = pm[0]+pm[1]+pm[2]+pm[3]+pm[4];
            float sp2m = p2m[0]+p2m[1]+p2m[2]+p2m[3]+p2m[4];
#pragma unroll
            for (int j = 0; j < KW; j++) {
                const float sm    = (float)smi;
                const float rden  = __fdividef(1.0f, fmaxf(sm, 1.0f));
                const float pmean = spm * rden;
                const float pvar  = sp2m * rden - pmean * pmean;
                const float tmean = (float)stmi * rden;
                const float tvar  = tmean - tmean * tmean;
                const float d = pvar - tvar;
                acc_mse[j] += d * d;
                vmask |= (unsigned)(smi != 0) << j;
                if (j < KW - 1) {
                    smi  += mv[j+WIN] - mv[j];
                    stmi += tm[j+WIN] - tm[j];
                    spm  += pm[j+WIN] - pm[j];
                    sp2m += p2m[j+WIN] - p2m[j];
                }
            }
        }
    }

    // Partials: one float4 of mse, one validity byte per thread (coalesced).
    *(float4*)&g_part_mse[blockIdx.y * LL + base] =
        make_float4(acc_mse[0], acc_mse[1], acc_mse[2], acc_mse[3]);
    g_valid[blockIdx.y * VBYTES + (base >> 2)] = (unsigned char)vmask;
}

// Single reduce kernel: 64 blocks x 256 threads. Each thread owns one window,
// sums 64 group-partials; block partial combined via 2 float atomics; the
// 64th block (ticket) writes the result and resets state.
__global__ __launch_bounds__(256)
void bcl_reduce_kernel(float* __restrict__ out)
{
    const int w = blockIdx.x * 256 + threadIdx.x;

    // Validity bytes for this block's 256 windows = 64 bytes; OR across groups.
    __shared__ unsigned char svalid[64];
    if (threadIdx.x < 64) {
        const int bidx = blockIdx.x * 64 + threadIdx.x;
        unsigned v = 0;
#pragma unroll 8
        for (int bg = 0; bg < BGROUPS; bg++)
            v |= (unsigned)g_valid[bg * VBYTES + bidx];
        svalid[threadIdx.x] = (unsigned char)v;
    }
    __syncthreads();

    float mse_total = 0.f;
#pragma unroll 8
    for (int bg = 0; bg < BGROUPS; bg++)
        mse_total += g_part_mse[bg * LL + w];

    float lmse = 0.f, lcnt = 0.f;
    if (w < NW && ((svalid[threadIdx.x >> 2] >> (w & 3)) & 1)) {
        lmse = mse_total * (1.0f / (float)BB_B);
        lcnt = 1.f;
    }

#pragma unroll
    for (int o = 16; o > 0; o >>= 1) {
        lmse += __shfl_down_sync(0xffffffffu, lmse, o);
        lcnt += __shfl_down_sync(0xffffffffu, lcnt, o);
    }
    __shared__ float smse[8], scnt[8];
    const int wid = threadIdx.x >> 5, lid = threadIdx.x & 31;
    if (lid == 0) { smse[wid] = lmse; scnt[wid] = lcnt; }
    __syncthreads();

    __shared__ unsigned s_ticket;
    if (threadIdx.x == 0) {
        float a = 0.f, c = 0.f;
#pragma unroll
        for (int i = 0; i < 8; i++) { a += smse[i]; c += scnt[i]; }
        atomicAdd(&g_acc[0], a);
        atomicAdd(&g_acc[1], c);
        __threadfence();
        s_ticket = atomicAdd(&g_ticket, 1u);
    }
    __syncthreads();

    if (s_ticket == RBLOCKS - 1 && threadIdx.x == 0) {
        __threadfence();
        const float a = g_acc[0];
        const float c = g_acc[1];
        out[0] = a / fmaxf(c, 1.0f);   // CONSISTENCY_WEIGHT == 1.0
        g_acc[0] = 0.f;                // restore pre-launch state for replay
        g_acc[1] = 0.f;
        g_ticket = 0u;
    }
}

extern "C" void kernel_launch(void* const* d_in, const int* in_sizes, int n_in,
                              void* d_out, int out_size)
{
    const float* preds   = (const float*)d_in[0];
    const int*   targets = (const int*)  d_in[1];
    const int*   mask    = (const int*)  d_in[2];

    dim3 gridA(NCHUNK, BGROUPS);             // 32 x 64 = 2048 blocks
    bcl_accum_kernel<<<gridA, THREADS>>>(preds, targets, mask);
    bcl_reduce_kernel<<<RBLOCKS, 256>>>((float*)d_out);
}

// round 14
// speedup vs baseline: 1.2371x; 1.0331x over previous
#include <cuda_runtime.h>

// BoundaryConsistencyLoss — atomic-accumulate + tiny-final version.
// K1: direct-from-global register-sliding accum (KW=4, 1-deep row prefetch);
//     per-window atomicAdd of d^2 partials + atomicOr validity. NO fences.
// K2: 128x128 gate+reduce, 2 atomics + ticket, writes out, resets scratch.
// B=512, L=16384, C=2, window=5.
//
// p = softmax(pred,-1)[...,1] = sigmoid(p1-p0)
// Window sums (w=5) of m, t*m (int) and p*m, p^2*m (float); t in {0,1} => st2m==stm.
// pvar = sp2m/denom - pmean^2 ; tvar = tmean*(1-tmean)  (exact; msum==0 => both 0).
// valid_w = (sum_b msum > 0) === OR over batches of (window has any mask).
//
// Replay determinism: g_win_mse/g_win_valid/g_acc/g_ticket are zero at module
// load; K2 re-zeroes everything it consumed, so each graph replay starts from
// identical state. Float-atomic ordering jitter ~1e-7 << 1e-3 tolerance.

#define BB_B      512
#define LL        16384
#define WIN       5
#define NW        (LL - WIN + 1)            // 16380
#define THREADS   128
#define KW        4
#define WCHUNK    (THREADS * KW)            // 512
#define NCHUNK    (LL / WCHUNK)             // 32
#define BGROUPS   64
#define BPG       (BB_B / BGROUPS)          // 8
#define NE        (KW + WIN - 1)            // 8 elements per thread per row
#define FBLOCKS   128

__device__ float    g_win_mse[LL];          // per-window sum over all batches of d^2
__device__ unsigned g_win_valid[LL / 32];   // per-window any-mask bit
__device__ float    g_acc[2];
__device__ unsigned g_ticket;

__device__ __forceinline__ float fsigmoid(float x) {
    return __fdividef(1.0f, 1.0f + __expf(-x));
}

struct RowRegs {
    float4 pr[4];          // 8 pred pairs
    int4   tt[2], mm[2];   // 8 targets, 8 masks
};

__device__ __forceinline__ void load_row(RowRegs& r,
                                         const float* __restrict__ preds,
                                         const int* __restrict__ targets,
                                         const int* __restrict__ mask,
                                         size_t rb, int base)
{
    const float4* p4 = (const float4*)preds + ((rb + (size_t)base) >> 1);
    const int4*   t4 = (const int4*)(targets + rb + base);
    const int4*   m4 = (const int4*)(mask    + rb + base);
#pragma unroll
    for (int q = 0; q < 4; q++) r.pr[q] = __ldg(&p4[q]);
#pragma unroll
    for (int q = 0; q < 2; q++) { r.tt[q] = __ldg(&t4[q]); r.mm[q] = __ldg(&m4[q]); }
}

__global__ __launch_bounds__(THREADS)
void bcl_accum_kernel(const float* __restrict__ preds,
                      const int*   __restrict__ targets,
                      const int*   __restrict__ mask)
{
    const int tid  = threadIdx.x;
    const int w0   = blockIdx.x * WCHUNK;
    const int base = w0 + tid * KW;
    const int b0   = blockIdx.y * BPG;
    const bool interior = (base + NE) <= LL;   // false only for last thread of last chunk

    float acc_mse[KW];
#pragma unroll
    for (int j = 0; j < KW; j++) acc_mse[j] = 0.f;
    unsigned vmask = 0;                        // bit j: window base+j had any mask

    if (interior) {
        RowRegs cur, nxt;
        load_row(cur, preds, targets, mask, (size_t)b0 * LL, base);

#pragma unroll
        for (int bi = 0; bi < BPG; bi++) {
            if (bi + 1 < BPG)
                load_row(nxt, preds, targets, mask, (size_t)(b0 + bi + 1) * LL, base);

            float pv[NE];
            int   mv[NE], tv[NE];
#pragma unroll
            for (int q = 0; q < 4; q++) {
                pv[q*2+0] = fsigmoid(cur.pr[q].y - cur.pr[q].x);
                pv[q*2+1] = fsigmoid(cur.pr[q].w - cur.pr[q].z);
            }
#pragma unroll
            for (int q = 0; q < 2; q++) {
                tv[q*4+0] = cur.tt[q].x; tv[q*4+1] = cur.tt[q].y;
                tv[q*4+2] = cur.tt[q].z; tv[q*4+3] = cur.tt[q].w;
                mv[q*4+0] = cur.mm[q].x; mv[q*4+1] = cur.mm[q].y;
                mv[q*4+2] = cur.mm[q].z; mv[q*4+3] = cur.mm[q].w;
            }

            int   tm[NE];
            float pm[NE], p2m[NE];
#pragma unroll
            for (int e = 0; e < NE; e++) {
                const int mi = mv[e];
                tm[e]  = tv[e] & mi;
                const float fm = (float)mi;
                pm[e]  = pv[e] * fm;
                p2m[e] = pv[e] * pm[e];
            }

            int   smi  = mv[0]+mv[1]+mv[2]+mv[3]+mv[4];
            int   stmi = tm[0]+tm[1]+tm[2]+tm[3]+tm[4];
            float spm  = pm[0]+pm[1]+pm[2]+pm[3]+pm[4];
            float sp2m = p2m[0]+p2m[1]+p2m[2]+p2m[3]+p2m[4];

#pragma unroll
            for (int j = 0; j < KW; j++) {
                const float sm    = (float)smi;
                const float rden  = __fdividef(1.0f, fmaxf(sm, 1.0f));
                const float pmean = spm * rden;
                const float pvar  = sp2m * rden - pmean * pmean;
                const float tmean = (float)stmi * rden;
                const float tvar  = tmean - tmean * tmean;
                const float d = pvar - tvar;
                acc_mse[j] += d * d;
                vmask |= (unsigned)(smi != 0) << j;
                if (j < KW - 1) {
                    smi  += mv[j+WIN] - mv[j];
                    stmi += tm[j+WIN] - tm[j];
                    spm  += pm[j+WIN] - pm[j];
                    sp2m += p2m[j+WIN] - p2m[j];
                }
            }
            cur = nxt;
        }
    } else {
        // tail thread: guarded scalar path (rare, correctness only)
        for (int bi = 0; bi < BPG; bi++) {
            const size_t rb = (size_t)(b0 + bi) * LL;
            float pv[NE]; int mv[NE], tv[NE];
#pragma unroll
            for (int e = 0; e < NE; e++) {
                const int idx = base + e;
                if (idx < LL) {
                    float a = __ldg(&preds[(rb + idx) * 2 + 0]);
                    float b = __ldg(&preds[(rb + idx) * 2 + 1]);
                    pv[e] = fsigmoid(b - a);
                    tv[e] = __ldg(&targets[rb + idx]);
                    mv[e] = __ldg(&mask[rb + idx]);
                } else { pv[e] = 0.f; tv[e] = 0; mv[e] = 0; }
            }
            int tm[NE]; float pm[NE], p2m[NE];
#pragma unroll
            for (int e = 0; e < NE; e++) {
                const int mi = mv[e];
                tm[e] = tv[e] & mi;
                const float fm = (float)mi;
                pm[e] = pv[e] * fm;
                p2m[e] = pv[e] * pm[e];
            }
            int   smi  = mv[0]+mv[1]+mv[2]+mv[3]+mv[4];
            int   stmi = tm[0]+tm[1]+tm[2]+tm[3]+tm[4];
            float spm  = pm[0]+pm[1]+pm[2]+pm[3]+pm[4];
            float sp2m = p2m[0]+p2m[1]+p2m[2]+p2m[3]+p2m[4];
#pragma unroll
            for (int j = 0; j < KW; j++) {
                const float sm    = (float)smi;
                const float rden  = __fdividef(1.0f, fmaxf(sm, 1.0f));
                const float pmean = spm * rden;
                const float pvar  = sp2m * rden - pmean * pmean;
                const float tmean = (float)stmi * rden;
                const float tvar  = tmean - tmean * tmean;
                const float d = pvar - tvar;
                acc_mse[j] += d * d;
                vmask |= (unsigned)(smi != 0) << j;
                if (j < KW - 1) {
                    smi  += mv[j+WIN] - mv[j];
                    stmi += tm[j+WIN] - tm[j];
                    spm  += pm[j+WIN] - pm[j];
                    sp2m += p2m[j+WIN] - p2m[j];
                }
            }
        }
    }

    // Fire-and-forget global accumulation. 64 colliding blocks per address
    // spread over 16K addresses / 184 LTS -> negligible serialization.
    // NO fence here (R12 lesson: per-thread __threadfence destroys L1).
    float* wm = &g_win_mse[base];
    atomicAdd(&wm[0], acc_mse[0]);
    atomicAdd(&wm[1], acc_mse[1]);
    atomicAdd(&wm[2], acc_mse[2]);
    atomicAdd(&wm[3], acc_mse[3]);
    if (vmask)
        atomicOr(&g_win_valid[base >> 5], vmask << (base & 31));
}

// Final: 128 blocks x 128 threads, one window per thread. Gate by validity,
// block-reduce, combine via atomics + ticket; last block writes and resets.
__global__ __launch_bounds__(THREADS)
void bcl_final_kernel(float* __restrict__ out)
{
    const int tid = threadIdx.x;
    const int w   = blockIdx.x * THREADS + tid;

    const float    mv = g_win_mse[w];
    const unsigned vw = g_win_valid[w >> 5];
    __syncthreads();                       // all reads of g_win_valid done
    g_win_mse[w] = 0.f;                    // reset for next replay
    if ((w & 31) == 0) g_win_valid[w >> 5] = 0u;

    float lmse = 0.f, lcnt = 0.f;
    if (w < NW && ((vw >> (w & 31)) & 1u)) {
        lmse = mv * (1.0f / (float)BB_B);
        lcnt = 1.f;
    }

#pragma unroll
    for (int o = 16; o > 0; o >>= 1) {
        lmse += __shfl_down_sync(0xffffffffu, lmse, o);
        lcnt += __shfl_down_sync(0xffffffffu, lcnt, o);
    }
    __shared__ float smse[4], scnt[4];
    const int wid = tid >> 5, lid = tid & 31;
    if (lid == 0) { smse[wid] = lmse; scnt[wid] = lcnt; }
    __syncthreads();

    __shared__ unsigned s_ticket;
    if (tid == 0) {
        const float a = smse[0] + smse[1] + smse[2] + smse[3];
        const float c = scnt[0] + scnt[1] + scnt[2] + scnt[3];
        atomicAdd(&g_acc[0], a);
        atomicAdd(&g_acc[1], c);
        __threadfence();
        s_ticket = atomicAdd(&g_ticket, 1u);
        if (s_ticket == FBLOCKS - 1) {
            __threadfence();
            out[0] = g_acc[0] / fmaxf(g_acc[1], 1.0f);  // weight == 1.0
            g_acc[0] = 0.f;
            g_acc[1] = 0.f;
            g_ticket = 0u;
        }
    }
}

extern "C" void kernel_launch(void* const* d_in, const int* in_sizes, int n_in,
                              void* d_out, int out_size)
{
    const float* preds   = (const float*)d_in[0];
    const int*   targets = (const int*)  d_in[1];
    const int*   mask    = (const int*)  d_in[2];

    dim3 gridA(NCHUNK, BGROUPS);             // 32 x 64 = 2048 blocks
    bcl_accum_kernel<<<gridA, THREADS>>>(preds, targets, mask);
    bcl_final_kernel<<<FBLOCKS, THREADS>>>((float*)d_out);
}

// round 15
// speedup vs baseline: 1.3895x; 1.1232x over previous
#include <cuda_runtime.h>

// BoundaryConsistencyLoss — persistent single-wave accum + single-block final.
// K1: 1480 blocks (= 148 SMs x 10) x 128 thr, static stride over 2048 units
//     (32 chunks x 64 row-groups of 8). Register-sliding windows (KW=4),
//     1-deep row prefetch, per-window atomicAdd(d^2) + warp-aggregated
//     atomicOr validity. No fences (kernel boundary provides visibility).
// K2: ONE block x 1024 thr: gate+reduce 16K windows, write out, reset scratch.
// B=512, L=16384, C=2, window=5.
//
// p = softmax(pred,-1)[...,1] = sigmoid(p1-p0)
// Window sums (w=5) of m, t*m (int) and p*m, p^2*m (float); t in {0,1} => st2m==stm.
// pvar = sp2m/denom - pmean^2 ; tvar = tmean*(1-tmean)  (exact; msum==0 => both 0).
// valid_w = (sum_b msum > 0) === OR over batches of (window has any mask).
//
// Replay determinism: g_win_mse/g_win_valid are zero at module load; K2
// re-zeroes them every launch. No tickets/counters anywhere. Float-atomic
// ordering jitter ~1e-7 << 1e-3 tolerance.

#define BB_B      512
#define LL        16384
#define WIN       5
#define NW        (LL - WIN + 1)            // 16380
#define THREADS   128
#define KW        4
#define WCHUNK    (THREADS * KW)            // 512
#define NCHUNK    (LL / WCHUNK)             // 32
#define UBPG      8                         // rows per unit
#define NGROUPS   (BB_B / UBPG)             // 64
#define NUNITS    (NCHUNK * NGROUPS)        // 2048
#define GRID      1480                      // 148 SMs x 10 blocks: one full wave
#define NE        (KW + WIN - 1)            // 8 elements per thread per row

__device__ float    g_win_mse[LL];          // per-window sum over all batches of d^2
__device__ unsigned g_win_valid[LL / 32];   // per-window any-mask bit

__device__ __forceinline__ float fsigmoid(float x) {
    return __fdividef(1.0f, 1.0f + __expf(-x));
}

struct RowRegs {
    float4 pr[4];          // 8 pred pairs
    int4   tt[2], mm[2];   // 8 targets, 8 masks
};

__device__ __forceinline__ void load_row(RowRegs& r,
                                         const float* __restrict__ preds,
                                         const int* __restrict__ targets,
                                         const int* __restrict__ mask,
                                         size_t rb, int base)
{
    const float4* p4 = (const float4*)preds + ((rb + (size_t)base) >> 1);
    const int4*   t4 = (const int4*)(targets + rb + base);
    const int4*   m4 = (const int4*)(mask    + rb + base);
#pragma unroll
    for (int q = 0; q < 4; q++) r.pr[q] = __ldg(&p4[q]);
#pragma unroll
    for (int q = 0; q < 2; q++) { r.tt[q] = __ldg(&t4[q]); r.mm[q] = __ldg(&m4[q]); }
}

__global__ __launch_bounds__(THREADS, 10)
void bcl_accum_kernel(const float* __restrict__ preds,
                      const int*   __restrict__ targets,
                      const int*   __restrict__ mask)
{
    const int tid = threadIdx.x;

    for (int u = blockIdx.x; u < NUNITS; u += GRID) {
        const int chunk = u & (NCHUNK - 1);
        const int grp   = u >> 5;                 // / NCHUNK
        const int base  = chunk * WCHUNK + tid * KW;
        const int b0    = grp * UBPG;
        const bool interior = (base + NE) <= LL;  // false only for last thread of last chunk

        float acc_mse[KW];
#pragma unroll
        for (int j = 0; j < KW; j++) acc_mse[j] = 0.f;
        unsigned vmask = 0;                       // bit j: window base+j had any mask

        if (interior) {
            RowRegs cur, nxt;
            load_row(cur, preds, targets, mask, (size_t)b0 * LL, base);

#pragma unroll
            for (int bi = 0; bi < UBPG; bi++) {
                if (bi + 1 < UBPG)
                    load_row(nxt, preds, targets, mask, (size_t)(b0 + bi + 1) * LL, base);

                float pv[NE];
                int   mv[NE], tv[NE];
#pragma unroll
                for (int q = 0; q < 4; q++) {
                    pv[q*2+0] = fsigmoid(cur.pr[q].y - cur.pr[q].x);
                    pv[q*2+1] = fsigmoid(cur.pr[q].w - cur.pr[q].z);
                }
#pragma unroll
                for (int q = 0; q < 2; q++) {
                    tv[q*4+0] = cur.tt[q].x; tv[q*4+1] = cur.tt[q].y;
                    tv[q*4+2] = cur.tt[q].z; tv[q*4+3] = cur.tt[q].w;
                    mv[q*4+0] = cur.mm[q].x; mv[q*4+1] = cur.mm[q].y;
                    mv[q*4+2] = cur.mm[q].z; mv[q*4+3] = cur.mm[q].w;
                }

                int   tm[NE];
                float pm[NE], p2m[NE];
#pragma unroll
                for (int e = 0; e < NE; e++) {
                    const int mi = mv[e];
                    tm[e]  = tv[e] & mi;
                    const float fm = (float)mi;
                    pm[e]  = pv[e] * fm;
                    p2m[e] = pv[e] * pm[e];
                }

                int   smi  = mv[0]+mv[1]+mv[2]+mv[3]+mv[4];
                int   stmi = tm[0]+tm[1]+tm[2]+tm[3]+tm[4];
                float spm  = pm[0]+pm[1]+pm[2]+pm[3]+pm[4];
                float sp2m = p2m[0]+p2m[1]+p2m[2]+p2m[3]+p2m[4];

#pragma unroll
                for (int j = 0; j < KW; j++) {
                    const float sm    = (float)smi;
                    const float rden  = __fdividef(1.0f, fmaxf(sm, 1.0f));
                    const float pmean = spm * rden;
                    const float pvar  = sp2m * rden - pmean * pmean;
                    const float tmean = (float)stmi * rden;
                    const float tvar  = tmean - tmean * tmean;
                    const float d = pvar - tvar;
                    acc_mse[j] += d * d;
                    vmask |= (unsigned)(smi != 0) << j;
                    if (j < KW - 1) {
                        smi  += mv[j+WIN] - mv[j];
                        stmi += tm[j+WIN] - tm[j];
                        spm  += pm[j+WIN] - pm[j];
                        sp2m += p2m[j+WIN] - p2m[j];
                    }
                }
                cur = nxt;
            }
        } else {
            // tail thread: guarded scalar path (rare, correctness only)
            for (int bi = 0; bi < UBPG; bi++) {
                const size_t rb = (size_t)(b0 + bi) * LL;
                float pv[NE]; int mv[NE], tv[NE];
#pragma unroll
                for (int e = 0; e < NE; e++) {
                    const int idx = base + e;
                    if (idx < LL) {
                        float a = __ldg(&preds[(rb + idx) * 2 + 0]);
                        float b = __ldg(&preds[(rb + idx) * 2 + 1]);
                        pv[e] = fsigmoid(b - a);
                        tv[e] = __ldg(&targets[rb + idx]);
                        mv[e] = __ldg(&mask[rb + idx]);
                    } else { pv[e] = 0.f; tv[e] = 0; mv[e] = 0; }
                }
                int tm[NE]; float pm[NE], p2m[NE];
#pragma unroll
                for (int e = 0; e < NE; e++) {
                    const int mi = mv[e];
                    tm[e] = tv[e] & mi;
                    const float fm = (float)mi;
                    pm[e] = pv[e] * fm;
                    p2m[e] = pv[e] * pm[e];
                }
                int   smi  = mv[0]+mv[1]+mv[2]+mv[3]+mv[4];
                int   stmi = tm[0]+tm[1]+tm[2]+tm[3]+tm[4];
                float spm  = pm[0]+pm[1]+pm[2]+pm[3]+pm[4];
                float sp2m = p2m[0]+p2m[1]+p2m[2]+p2m[3]+p2m[4];
#pragma unroll
                for (int j = 0; j < KW; j++) {
                    const float sm    = (float)smi;
                    const float rden  = __fdividef(1.0f, fmaxf(sm, 1.0f));
                    const float pmean = spm * rden;
                    const float pvar  = sp2m * rden - pmean * pmean;
                    const float tmean = (float)stmi * rden;
                    const float tvar  = tmean - tmean * tmean;
                    const float d = pvar - tvar;
                    acc_mse[j] += d * d;
                    vmask |= (unsigned)(smi != 0) << j;
                    if (j < KW - 1) {
                        smi  += mv[j+WIN] - mv[j];
                        stmi += tm[j+WIN] - tm[j];
                        spm  += pm[j+WIN] - pm[j];
                        sp2m += p2m[j+WIN] - p2m[j];
                    }
                }
            }
        }

        // Fire-and-forget accumulation (no fences).
        float* wm = &g_win_mse[base];
        atomicAdd(&wm[0], acc_mse[0]);
        atomicAdd(&wm[1], acc_mse[1]);
        atomicAdd(&wm[2], acc_mse[2]);
        atomicAdd(&wm[3], acc_mse[3]);

        // Warp-aggregated validity OR: 8 consecutive lanes share one 32-bit word.
        unsigned vword = vmask << (base & 31);
        vword |= __shfl_xor_sync(0xffffffffu, vword, 1);
        vword |= __shfl_xor_sync(0xffffffffu, vword, 2);
        vword |= __shfl_xor_sync(0xffffffffu, vword, 4);
        if ((tid & 7) == 0 && vword)
            atomicOr(&g_win_valid[base >> 5], vword);
    }
}

// Final: single block, 1024 threads. Gate+reduce all windows, write out,
// reset scratch for the next graph replay.
__global__ __launch_bounds__(1024)
void bcl_final_kernel(float* __restrict__ out)
{
    const int tid = threadIdx.x;
    float lmse = 0.f, lcnt = 0.f;

    const float4* wm4 = (const float4*)g_win_mse;
#pragma unroll
    for (int i = tid; i < LL / 4; i += 1024) {
        const float4   v  = wm4[i];
        const unsigned vw = g_win_valid[i >> 3];
        const int wbase = i * 4;
        const float* vv = &v.x;
#pragma unroll
        for (int k = 0; k < 4; k++) {
            const int w = wbase + k;
            if (w < NW && ((vw >> (w & 31)) & 1u)) {
                lmse += vv[k];
                lcnt += 1.f;
            }
        }
        ((float4*)g_win_mse)[i] = make_float4(0.f, 0.f, 0.f, 0.f);  // reset
    }
    __syncthreads();                 // all validity reads complete
    if (tid < LL / 32) g_win_valid[tid] = 0u;

#pragma unroll
    for (int o = 16; o > 0; o >>= 1) {
        lmse += __shfl_down_sync(0xffffffffu, lmse, o);
        lcnt += __shfl_down_sync(0xffffffffu, lcnt, o);
    }
    __shared__ float smse[32], scnt[32];
    const int wid = tid >> 5, lid = tid & 31;
    if (lid == 0) { smse[wid] = lmse; scnt[wid] = lcnt; }
    __syncthreads();
    if (wid == 0) {
        float a = (lid < 32) ? smse[lid] : 0.f;
        float c = (lid < 32) ? scnt[lid] : 0.f;
#pragma unroll
        for (int o = 16; o > 0; o >>= 1) {
            a += __shfl_down_sync(0xffffffffu, a, o);
            c += __shfl_down_sync(0xffffffffu, c, o);
        }
        if (lid == 0)
            out[0] = (a * (1.0f / (float)BB_B)) / fmaxf(c, 1.0f);  // weight == 1.0
    }
}

extern "C" void kernel_launch(void* const* d_in, const int* in_sizes, int n_in,
                              void* d_out, int out_size)
{
    const float* preds   = (const float*)d_in[0];
    const int*   targets = (const int*)  d_in[1];
    const int*   mask    = (const int*)  d_in[2];

    bcl_accum_kernel<<<GRID, THREADS>>>(preds, targets, mask);
    bcl_final_kernel<<<1, 1024>>>((float*)d_out);
}